// round 17
// baseline (speedup 1.0000x reference)
#include <cuda_runtime.h>
#include <cuda_fp16.h>
#include <math.h>
#include <stdint.h>

typedef __half half_t;

#define NTOK 4096
#define DIM_ 1024
#define LSEQ 1024
#define HID_ 4096
#define EPS_ 1e-5f
#define SCALE_ 0.125f

// ---------------------------------------------------------------------------
// Device scratch (no runtime allocation allowed)
// ---------------------------------------------------------------------------
__device__ float g_skipout[NTOK * DIM_];
__device__ float g_xln1   [NTOK * DIM_];
__device__ float g_x2     [NTOK * DIM_];
__device__ float g_tmp    [NTOK * DIM_];

__device__ half_t g_xh  [NTOK * DIM_];
__device__ half_t g_skh [NTOK * DIM_];
__device__ half_t g_x1h [NTOK * DIM_];
__device__ half_t g_qkvh[NTOK * 3 * DIM_];
__device__ half_t g_obh [NTOK * DIM_];
__device__ half_t g_x2h [NTOK * DIM_];
__device__ half_t g_hh  [(size_t)NTOK * HID_];
// transposed weights [N][K] fp16
__device__ half_t g_wsk [DIM_ * 2 * DIM_];
__device__ half_t g_wqkv[3 * DIM_ * DIM_];
__device__ half_t g_wpr [DIM_ * DIM_];
__device__ half_t g_wf1 [(size_t)HID_ * DIM_];
__device__ half_t g_wf2 [(size_t)DIM_ * HID_];

// ---------------------------------------------------------------------------
// PTX helpers (plain-sm_103-legal)
// ---------------------------------------------------------------------------
__device__ __forceinline__ uint32_t smem_u32(const void* p) {
    uint32_t a;
    asm("{ .reg .u64 t; cvta.to.shared.u64 t, %1; cvt.u32.u64 %0, t; }"
        : "=r"(a) : "l"(p));
    return a;
}
__device__ __forceinline__ void cp16(uint32_t dst, const void* src) {
    asm volatile("cp.async.cg.shared.global [%0], [%1], 16;"
                 :: "r"(dst), "l"(src));
}
__device__ __forceinline__ void cp_commit() {
    asm volatile("cp.async.commit_group;" ::: "memory");
}
template<int N>
__device__ __forceinline__ void cp_wait() {
    asm volatile("cp.async.wait_group %0;" :: "n"(N) : "memory");
}
__device__ __forceinline__ void ldm_x4(uint32_t& r0, uint32_t& r1,
                                       uint32_t& r2, uint32_t& r3, uint32_t a) {
    asm volatile("ldmatrix.sync.aligned.m8n8.x4.shared.b16 {%0,%1,%2,%3}, [%4];"
                 : "=r"(r0), "=r"(r1), "=r"(r2), "=r"(r3) : "r"(a));
}
__device__ __forceinline__ void ldm_x4_t(uint32_t& r0, uint32_t& r1,
                                         uint32_t& r2, uint32_t& r3, uint32_t a) {
    asm volatile("ldmatrix.sync.aligned.m8n8.x4.trans.shared.b16 {%0,%1,%2,%3}, [%4];"
                 : "=r"(r0), "=r"(r1), "=r"(r2), "=r"(r3) : "r"(a));
}
__device__ __forceinline__ void mma_f16(
    float& c0, float& c1, float& c2, float& c3,
    uint32_t a0, uint32_t a1, uint32_t a2, uint32_t a3,
    uint32_t b0, uint32_t b1)
{
    asm volatile(
        "mma.sync.aligned.m16n8k16.row.col.f32.f16.f16.f32 "
        "{%0,%1,%2,%3}, {%4,%5,%6,%7}, {%8,%9}, {%0,%1,%2,%3};"
        : "+f"(c0), "+f"(c1), "+f"(c2), "+f"(c3)
        : "r"(a0), "r"(a1), "r"(a2), "r"(a3), "r"(b0), "r"(b1));
}
// pack two floats into fp16x2 bits: lo -> low half, hi -> high half
__device__ __forceinline__ uint32_t f2_to_h2(float lo, float hi) {
    uint32_t r;
    asm("cvt.rn.f16x2.f32 %0, %1, %2;" : "=r"(r) : "f"(hi), "f"(lo));
    return r;
}

// ---------------------------------------------------------------------------
// fp16 tensor-core GEMM, 3-stage cp.async pipeline, dynamic smem.
// C[M,N] = alpha*(A[M,K] @ B[N,K]^T) (+bias)(+gelu). BM=BN=128, BK=32,
// 8 warps (2x4), 2 CTAs/SM. One barrier per chunk (no trailing sync).
// ---------------------------------------------------------------------------
#define G_PAD 40
#define G_NS 3
#define G_SMEM (G_NS * (128 + 128) * G_PAD * 2)

struct GemmP {
    const half_t *a, *a2, *b;
    const float* bias;
    float* out_f;
    half_t* out_h;
    int K, lda, ldb, ldc, ksplit;
    float alpha;
};

template<bool CONCAT, bool BIAS, bool GELU, bool OUTF32>
__global__ void __launch_bounds__(256, 2) gemm_fp16(GemmP p) {
    constexpr int BK = 32, PAD = G_PAD;
    constexpr int MT = 4, NT = 4;            // per-warp 64x32 (2x4 warp grid)

    extern __shared__ char gsm[];
    half_t* As = (half_t*)gsm;               // [NS][128][PAD]
    half_t* Bs = As + G_NS * 128 * PAD;      // [NS][128][PAD]

    const int tid = threadIdx.x, lane = tid & 31, warp = tid >> 5;
    const int wm = warp >> 2, wn = warp & 3;
    const int g = lane >> 2, tig = lane & 3;
    const int bm = blockIdx.y * 128, bn = blockIdx.x * 128;

    const half_t* Az = p.a;
    const half_t* Bz = p.b;

    const uint32_t sA = smem_u32(As), sB = smem_u32(Bs);
    const int nchunk = p.K / BK;

    auto load_tile = [&](int st, int c) {
        const half_t* asrc; int ka;
        if (CONCAT && c * BK >= p.ksplit) { asrc = p.a2; ka = c * BK - p.ksplit; }
        else                               { asrc = Az;  ka = c * BK; }
#pragma unroll
        for (int u = 0; u < 2; u++) {
            int ch = u * 256 + tid;
            int row = ch >> 2, o = ch & 3;
            cp16(sA + ((st * 128 + row) * PAD + o * 8) * 2,
                 asrc + (size_t)(bm + row) * p.lda + ka + o * 8);
        }
#pragma unroll
        for (int u = 0; u < 2; u++) {
            int ch = u * 256 + tid;
            int row = ch >> 2, o = ch & 3;
            cp16(sB + ((st * 128 + row) * PAD + o * 8) * 2,
                 Bz + (size_t)(bn + row) * p.ldb + c * BK + o * 8);
        }
        cp_commit();
    };

    float acc[MT][NT][4];
#pragma unroll
    for (int i = 0; i < MT; i++)
#pragma unroll
        for (int j = 0; j < NT; j++)
#pragma unroll
            for (int r = 0; r < 4; r++) acc[i][j][r] = 0.f;

    load_tile(0, 0);
    load_tile(1, 1);

    const int a_row = lane & 15;
    const int a_ko  = (lane >> 4) * 8;
    const int b_ro  = (lane >> 4) * 8 + (lane & 7);
    const int b_ko  = ((lane >> 3) & 1) * 8;

    for (int c = 0; c < nchunk; c++) {
        const int st = c % G_NS;
        if (c + 1 >= nchunk) cp_wait<0>(); else cp_wait<1>();
        __syncthreads();
        if (c + 2 < nchunk) load_tile((c + 2) % G_NS, c + 2);

#pragma unroll
        for (int ks = 0; ks < 2; ks++) {
            const int kk = ks * 16;
            uint32_t a[MT][4], b[NT][2];
#pragma unroll
            for (int mt = 0; mt < MT; mt++) {
                int row = wm * 64 + mt * 16 + a_row;
                uint32_t addr = sA + ((st * 128 + row) * PAD + kk + a_ko) * 2;
                ldm_x4(a[mt][0], a[mt][1], a[mt][2], a[mt][3], addr);
            }
#pragma unroll
            for (int pr = 0; pr < NT / 2; pr++) {
                int row = wn * 32 + pr * 16 + b_ro;
                uint32_t addr = sB + ((st * 128 + row) * PAD + kk + b_ko) * 2;
                ldm_x4(b[2 * pr][0], b[2 * pr][1],
                       b[2 * pr + 1][0], b[2 * pr + 1][1], addr);
            }
#pragma unroll
            for (int mt = 0; mt < MT; mt++)
#pragma unroll
                for (int nt = 0; nt < NT; nt++)
                    mma_f16(acc[mt][nt][0], acc[mt][nt][1],
                            acc[mt][nt][2], acc[mt][nt][3],
                            a[mt][0], a[mt][1], a[mt][2], a[mt][3],
                            b[nt][0], b[nt][1]);
        }
        // no trailing sync: 3-stage ring never overwrites a live buffer
    }

#pragma unroll
    for (int mt = 0; mt < MT; mt++) {
#pragma unroll
        for (int nt = 0; nt < NT; nt++) {
            int r0 = bm + wm * 64 + mt * 16 + g;
            int cn = bn + wn * 32 + nt * 8 + tig * 2;
            float bia0 = 0.f, bia1 = 0.f;
            if (BIAS) { bia0 = p.bias[cn]; bia1 = p.bias[cn + 1]; }
#pragma unroll
            for (int hf = 0; hf < 2; hf++) {
                int r = r0 + hf * 8;
                float v0 = acc[mt][nt][hf * 2 + 0] * p.alpha + bia0;
                float v1 = acc[mt][nt][hf * 2 + 1] * p.alpha + bia1;
                if (GELU) {
                    v0 = 0.5f * v0 * (1.f + erff(v0 * 0.70710678118654752f));
                    v1 = 0.5f * v1 * (1.f + erff(v1 * 0.70710678118654752f));
                }
                long off = (long)r * p.ldc + cn;
                if (OUTF32) {
                    float2 o; o.x = v0; o.y = v1;
                    *(float2*)(p.out_f + off) = o;
                } else {
                    __half2 o;
                    o.x = __float2half_rn(v0); o.y = __float2half_rn(v1);
                    *(__half2*)(p.out_h + off) = o;
                }
            }
        }
    }
}

// ---------------------------------------------------------------------------
// Fused flash attention (round-12, passing): per block = 128 q-rows x 1 head
// ---------------------------------------------------------------------------
#define FA_PAD 72
#define FA_SMEM ((128 * FA_PAD + 2 * 64 * FA_PAD + 2 * 64 * FA_PAD) * 2)

__global__ void __launch_bounds__(256) fattn_kernel(
    const half_t* __restrict__ qkv, half_t* __restrict__ o_out)
{
    extern __shared__ half_t fsm[];
    half_t* Qs = fsm;                          // [128][FA_PAD]
    half_t* Ks = Qs + 128 * FA_PAD;            // [2][64][FA_PAD]
    half_t* Vs = Ks + 2 * 64 * FA_PAD;         // [2][64][FA_PAD]

    const int tid = threadIdx.x, lane = tid & 31, w = tid >> 5;
    const int g = lane >> 2, tig = lane & 3;
    const int z = blockIdx.y, b = z >> 4, h = z & 15;
    const int i0 = blockIdx.x * 128;

    const half_t* qb = qkv + (size_t)(b * LSEQ) * 3072 + h * 64;
    const half_t* kb = qb + 1024;
    const half_t* vb = qb + 2048;

    const uint32_t sQ = smem_u32(Qs), sK = smem_u32(Ks), sV = smem_u32(Vs);

    auto load_kv = [&](int s, int j0) {
#pragma unroll
        for (int u = 0; u < 2; u++) {
            int ch = u * 256 + tid;
            int row = ch >> 3, off = (ch & 7) * 8;
            cp16(sK + ((s * 64 + row) * FA_PAD + off) * 2,
                 kb + (size_t)(j0 + row) * 3072 + off);
        }
#pragma unroll
        for (int u = 0; u < 2; u++) {
            int ch = u * 256 + tid;
            int row = ch >> 3, off = (ch & 7) * 8;
            cp16(sV + ((s * 64 + row) * FA_PAD + off) * 2,
                 vb + (size_t)(j0 + row) * 3072 + off);
        }
        cp_commit();
    };

#pragma unroll
    for (int u = 0; u < 4; u++) {
        int ch = u * 256 + tid;
        int row = ch >> 3, off = (ch & 7) * 8;
        cp16(sQ + (row * FA_PAD + off) * 2,
             qb + (size_t)(i0 + row) * 3072 + off);
    }
    load_kv(0, 0);
    load_kv(1, 64);

    float m0 = -1e30f, m1 = -1e30f, l0 = 0.f, l1 = 0.f;
    float oacc[8][4];
#pragma unroll
    for (int nt = 0; nt < 8; nt++)
#pragma unroll
        for (int r = 0; r < 4; r++) oacc[nt][r] = 0.f;

    const int a_row = lane & 15;
    const int a_ko  = (lane >> 4) * 8;
    const int b_ro  = (lane >> 4) * 8 + (lane & 7);
    const int b_ko  = ((lane >> 3) & 1) * 8;

    for (int c = 0; c < 16; c++) {
        const int s = c & 1;
        if (c == 15) cp_wait<0>(); else cp_wait<1>();
        __syncthreads();

        float sacc[8][4];
#pragma unroll
        for (int nt = 0; nt < 8; nt++)
#pragma unroll
            for (int r = 0; r < 4; r++) sacc[nt][r] = 0.f;

#pragma unroll
        for (int k4 = 0; k4 < 4; k4++) {
            const int kk = k4 * 16;
            uint32_t qa[4], kf[8][2];
            ldm_x4(qa[0], qa[1], qa[2], qa[3],
                   sQ + ((w * 16 + a_row) * FA_PAD + kk + a_ko) * 2);
#pragma unroll
            for (int pr = 0; pr < 4; pr++)
                ldm_x4(kf[2 * pr][0], kf[2 * pr][1],
                       kf[2 * pr + 1][0], kf[2 * pr + 1][1],
                       sK + ((s * 64 + pr * 16 + b_ro) * FA_PAD + kk + b_ko) * 2);
#pragma unroll
            for (int nt = 0; nt < 8; nt++)
                mma_f16(sacc[nt][0], sacc[nt][1], sacc[nt][2], sacc[nt][3],
                        qa[0], qa[1], qa[2], qa[3], kf[nt][0], kf[nt][1]);
        }

#pragma unroll
        for (int nt = 0; nt < 8; nt++)
#pragma unroll
            for (int r = 0; r < 4; r++) sacc[nt][r] *= SCALE_;

        float cm0 = -1e30f, cm1 = -1e30f;
#pragma unroll
        for (int nt = 0; nt < 8; nt++) {
            cm0 = fmaxf(cm0, fmaxf(sacc[nt][0], sacc[nt][1]));
            cm1 = fmaxf(cm1, fmaxf(sacc[nt][2], sacc[nt][3]));
        }
        cm0 = fmaxf(cm0, __shfl_xor_sync(0xffffffffu, cm0, 1));
        cm0 = fmaxf(cm0, __shfl_xor_sync(0xffffffffu, cm0, 2));
        cm1 = fmaxf(cm1, __shfl_xor_sync(0xffffffffu, cm1, 1));
        cm1 = fmaxf(cm1, __shfl_xor_sync(0xffffffffu, cm1, 2));

        float mn0 = fmaxf(m0, cm0), mn1 = fmaxf(m1, cm1);
        float cr0 = __expf(m0 - mn0), cr1 = __expf(m1 - mn1);
        m0 = mn0; m1 = mn1;

        float rs0 = 0.f, rs1 = 0.f;
#pragma unroll
        for (int nt = 0; nt < 8; nt++) {
            sacc[nt][0] = __expf(sacc[nt][0] - m0);
            sacc[nt][1] = __expf(sacc[nt][1] - m0);
            sacc[nt][2] = __expf(sacc[nt][2] - m1);
            sacc[nt][3] = __expf(sacc[nt][3] - m1);
            rs0 += sacc[nt][0] + sacc[nt][1];
            rs1 += sacc[nt][2] + sacc[nt][3];
        }
        rs0 += __shfl_xor_sync(0xffffffffu, rs0, 1);
        rs0 += __shfl_xor_sync(0xffffffffu, rs0, 2);
        rs1 += __shfl_xor_sync(0xffffffffu, rs1, 1);
        rs1 += __shfl_xor_sync(0xffffffffu, rs1, 2);
        l0 = l0 * cr0 + rs0;
        l1 = l1 * cr1 + rs1;

#pragma unroll
        for (int nt = 0; nt < 8; nt++) {
            oacc[nt][0] *= cr0; oacc[nt][1] *= cr0;
            oacc[nt][2] *= cr1; oacc[nt][3] *= cr1;
        }

        uint32_t pa[4][4];
#pragma unroll
        for (int kt = 0; kt < 4; kt++) {
            pa[kt][0] = f2_to_h2(sacc[2 * kt][0], sacc[2 * kt][1]);
            pa[kt][1] = f2_to_h2(sacc[2 * kt][2], sacc[2 * kt][3]);
            pa[kt][2] = f2_to_h2(sacc[2 * kt + 1][0], sacc[2 * kt + 1][1]);
            pa[kt][3] = f2_to_h2(sacc[2 * kt + 1][2], sacc[2 * kt + 1][3]);
        }

#pragma unroll
        for (int kt = 0; kt < 4; kt++) {
            uint32_t vf[8][2];
#pragma unroll
            for (int pr = 0; pr < 4; pr++)
                ldm_x4_t(vf[2 * pr][0], vf[2 * pr][1],
                         vf[2 * pr + 1][0], vf[2 * pr + 1][1],
                         sV + ((s * 64 + kt * 16 + a_row) * FA_PAD
                               + pr * 16 + a_ko) * 2);
#pragma unroll
            for (int nt = 0; nt < 8; nt++)
                mma_f16(oacc[nt][0], oacc[nt][1], oacc[nt][2], oacc[nt][3],
                        pa[kt][0], pa[kt][1], pa[kt][2], pa[kt][3],
                        vf[nt][0], vf[nt][1]);
        }

        __syncthreads();
        if (c + 2 < 16) load_kv(s, (c + 2) * 64);
    }

    const float li0 = 1.f / l0, li1 = 1.f / l1;
    const int row0 = b * LSEQ + i0 + w * 16 + g;
#pragma unroll
    for (int nt = 0; nt < 8; nt++) {
        const int col = h * 64 + nt * 8 + tig * 2;
        __half2 o0 = __floats2half2_rn(oacc[nt][0] * li0, oacc[nt][1] * li0);
        __half2 o1 = __floats2half2_rn(oacc[nt][2] * li1, oacc[nt][3] * li1);
        *(__half2*)(o_out + (size_t)row0 * DIM_ + col) = o0;
        *(__half2*)(o_out + (size_t)(row0 + 8) * DIM_ + col) = o1;
    }
}

// ---------------------------------------------------------------------------
// fp32 -> fp16 elementwise convert
// ---------------------------------------------------------------------------
__global__ __launch_bounds__(256)
void cvt_half(const float* __restrict__ in, half_t* __restrict__ out) {
    size_t i = ((size_t)blockIdx.x * 256 + threadIdx.x) * 4;
    float4 x = *(const float4*)(in + i);
    __half2 a, b;
    a.x = __float2half_rn(x.x); a.y = __float2half_rn(x.y);
    b.x = __float2half_rn(x.z); b.y = __float2half_rn(x.w);
    *(__half2*)(out + i) = a;
    *(__half2*)(out + i + 2) = b;
}

// ---------------------------------------------------------------------------
// Weight transpose+convert: fp32 [K,N] -> fp16 [N][K].
// 64(k) x 32(n) tiles; smem stored [n][k] (pad 65, conflict-free);
// scalar smem reads (odd pad breaks float2 alignment), half2 global stores.
// grid (K/64, N/32), 256 threads.
// ---------------------------------------------------------------------------
__global__ __launch_bounds__(256)
void wtrans_kernel(const float* __restrict__ w, half_t* __restrict__ o,
                   int K, int N) {
    __shared__ float t2[32][65];               // [n][k]
    int k0 = blockIdx.x * 64, n0 = blockIdx.y * 32;
    int tx = threadIdx.x & 31, ty = threadIdx.x >> 5;
    // phase 1: read rows of w (k-major): w[k0+i][n0+tx], i = ty..63 step 8
    for (int i = ty; i < 64; i += 8)
        t2[tx][i] = w[(size_t)(k0 + i) * N + n0 + tx];
    __syncthreads();
    // phase 2: write o[n0+j][k0 + 2*tx .. +1] as half2 (scalar smem reads)
    for (int j = ty; j < 32; j += 8) {
        float v0 = t2[j][2 * tx];
        float v1 = t2[j][2 * tx + 1];
        __half2 h;
        h.x = __float2half_rn(v0); h.y = __float2half_rn(v1);
        *(__half2*)(o + (size_t)(n0 + j) * K + k0 + 2 * tx) = h;
    }
}

// ---------------------------------------------------------------------------
// LayerNorm (+residual): out fp32 (optional) + fp16 copy (optional)
// ---------------------------------------------------------------------------
__global__ __launch_bounds__(256)
void ln_kernel(const float* __restrict__ in, const float* __restrict__ res,
               const float* __restrict__ g, const float* __restrict__ b,
               float* __restrict__ out_f, half_t* __restrict__ out_h) {
    const size_t row = blockIdx.x;
    const int t = threadIdx.x;
    float4 x = ((const float4*)(in + row * DIM_))[t];
    if (res) {
        float4 r = ((const float4*)(res + row * DIM_))[t];
        x.x += r.x; x.y += r.y; x.z += r.z; x.w += r.w;
    }
    float s = x.x + x.y + x.z + x.w;
    float ss = x.x*x.x + x.y*x.y + x.z*x.z + x.w*x.w;
#pragma unroll
    for (int o = 16; o > 0; o >>= 1) {
        s  += __shfl_down_sync(0xffffffffu, s, o);
        ss += __shfl_down_sync(0xffffffffu, ss, o);
    }
    __shared__ float shs[8], shss[8], shm, shr;
    int w = t >> 5, lane = t & 31;
    if (lane == 0) { shs[w] = s; shss[w] = ss; }
    __syncthreads();
    if (t == 0) {
        float S = 0, SS = 0;
#pragma unroll
        for (int i = 0; i < 8; i++) { S += shs[i]; SS += shss[i]; }
        float m = S * (1.f / DIM_);
        shm = m; shr = rsqrtf(SS * (1.f / DIM_) - m * m + EPS_);
    }
    __syncthreads();
    float m = shm, rs = shr;
    float4 gg = ((const float4*)g)[t], bb = ((const float4*)b)[t];
    float4 o4;
    o4.x = (x.x-m)*rs*gg.x + bb.x; o4.y = (x.y-m)*rs*gg.y + bb.y;
    o4.z = (x.z-m)*rs*gg.z + bb.z; o4.w = (x.w-m)*rs*gg.w + bb.w;
    if (out_f) ((float4*)(out_f + row * DIM_))[t] = o4;
    if (out_h) {
        __half2 a, bb2;
        a.x = __float2half_rn(o4.x); a.y = __float2half_rn(o4.y);
        bb2.x = __float2half_rn(o4.z); bb2.y = __float2half_rn(o4.w);
        size_t i = row * DIM_ + t * 4;
        *(__half2*)(out_h + i) = a;
        *(__half2*)(out_h + i + 2) = bb2;
    }
}

// ---------------------------------------------------------------------------
// Launch
// ---------------------------------------------------------------------------
#define GA(v, sym) cudaGetSymbolAddress((void**)&v, sym)

extern "C" void kernel_launch(void* const* d_in, const int* in_sizes, int n_in,
                              void* d_out, int out_size) {
    const float* x      = (const float*)d_in[0];
    const float* skip   = (const float*)d_in[1];
    const float* skip_w = (const float*)d_in[2];
    const float* skip_b = (const float*)d_in[3];
    const float* ln1_g  = (const float*)d_in[4];
    const float* ln1_b  = (const float*)d_in[5];
    const float* qkv_w  = (const float*)d_in[6];
    const float* proj_w = (const float*)d_in[7];
    const float* proj_b = (const float*)d_in[8];
    const float* ln2_g  = (const float*)d_in[9];
    const float* ln2_b  = (const float*)d_in[10];
    const float* fc1_w  = (const float*)d_in[11];
    const float* fc1_b  = (const float*)d_in[12];
    const float* fc2_w  = (const float*)d_in[13];
    const float* fc2_b  = (const float*)d_in[14];
    const float* ln3_g  = (const float*)d_in[15];
    const float* ln3_b  = (const float*)d_in[16];
    float* out = (float*)d_out;

    float *skipout, *xln1, *x2, *tmp;
    GA(skipout, g_skipout); GA(xln1, g_xln1); GA(x2, g_x2); GA(tmp, g_tmp);
    half_t *xh,*skh,*x1h,*qkvh,*obh,*x2h,*hh;
    GA(xh,g_xh); GA(skh,g_skh); GA(x1h,g_x1h); GA(qkvh,g_qkvh);
    GA(obh,g_obh); GA(x2h,g_x2h); GA(hh,g_hh);
    half_t *wsk,*wqkv,*wpr,*wf1,*wf2;
    GA(wsk,g_wsk); GA(wqkv,g_wqkv); GA(wpr,g_wpr); GA(wf1,g_wf1); GA(wf2,g_wf2);

    cudaFuncSetAttribute(fattn_kernel,
                         cudaFuncAttributeMaxDynamicSharedMemorySize, FA_SMEM);
    cudaFuncSetAttribute(gemm_fp16<true, true, false,true>,  cudaFuncAttributeMaxDynamicSharedMemorySize, G_SMEM);
    cudaFuncSetAttribute(gemm_fp16<false,false,false,false>, cudaFuncAttributeMaxDynamicSharedMemorySize, G_SMEM);
    cudaFuncSetAttribute(gemm_fp16<false,true, false,true>,  cudaFuncAttributeMaxDynamicSharedMemorySize, G_SMEM);
    cudaFuncSetAttribute(gemm_fp16<false,true, true, false>, cudaFuncAttributeMaxDynamicSharedMemorySize, G_SMEM);

    // ---- prep: transpose+convert weights, convert inputs
    wtrans_kernel<<<dim3(32,32), 256>>>(skip_w, wsk, 2*DIM_, DIM_);
    wtrans_kernel<<<dim3(16,96), 256>>>(qkv_w,  wqkv, DIM_, 3*DIM_);
    wtrans_kernel<<<dim3(16,32), 256>>>(proj_w, wpr,  DIM_, DIM_);
    wtrans_kernel<<<dim3(16,128),256>>>(fc1_w,  wf1,  DIM_, HID_);
    wtrans_kernel<<<dim3(64,32), 256>>>(fc2_w,  wf2,  HID_, DIM_);
    cvt_half<<<NTOK*DIM_/1024, 256>>>(x,    xh);
    cvt_half<<<NTOK*DIM_/1024, 256>>>(skip, skh);

    GemmP p;

    // 1. skip-concat GEMM (K=2048, A switches x->skip at k=1024)
    memset(&p, 0, sizeof(p)); p.alpha = 1.f;
    p.a = xh; p.a2 = skh; p.b = wsk; p.bias = skip_b; p.out_f = skipout;
    p.K = 2048; p.lda = DIM_; p.ldb = 2048; p.ldc = DIM_; p.ksplit = 1024;
    gemm_fp16<true,true,false,true><<<dim3(8,32), 256, G_SMEM>>>(p);
    // 2. LN1 -> xln1 f32 + x1h fp16
    ln_kernel<<<NTOK,256>>>(skipout, nullptr, ln1_g, ln1_b, xln1, x1h);
    // 3. QKV GEMM -> qkvh fp16
    memset(&p, 0, sizeof(p)); p.alpha = 1.f;
    p.a = x1h; p.b = wqkv; p.out_h = qkvh;
    p.K = DIM_; p.lda = DIM_; p.ldb = DIM_; p.ldc = 3*DIM_;
    gemm_fp16<false,false,false,false><<<dim3(24,32), 256, G_SMEM>>>(p);
    // 4. fused flash attention -> obh fp16
    fattn_kernel<<<dim3(LSEQ/128, 64), 256, FA_SMEM>>>(qkvh, obh);
    // 5. proj -> tmp f32
    memset(&p, 0, sizeof(p)); p.alpha = 1.f;
    p.a = obh; p.b = wpr; p.bias = proj_b; p.out_f = tmp;
    p.K = DIM_; p.lda = DIM_; p.ldb = DIM_; p.ldc = DIM_;
    gemm_fp16<false,true,false,true><<<dim3(8,32), 256, G_SMEM>>>(p);
    // 6. LN2 over (tmp + xln1) -> x2 f32 + x2h fp16
    ln_kernel<<<NTOK,256>>>(tmp, xln1, ln2_g, ln2_b, x2, x2h);
    // 7. fc1 + bias + GELU -> hh fp16
    memset(&p, 0, sizeof(p)); p.alpha = 1.f;
    p.a = x2h; p.b = wf1; p.bias = fc1_b; p.out_h = hh;
    p.K = DIM_; p.lda = DIM_; p.ldb = DIM_; p.ldc = HID_;
    gemm_fp16<false,true,true,false><<<dim3(32,32), 256, G_SMEM>>>(p);
    // 8. fc2 -> tmp f32
    memset(&p, 0, sizeof(p)); p.alpha = 1.f;
    p.a = hh; p.b = wf2; p.bias = fc2_b; p.out_f = tmp;
    p.K = HID_; p.lda = HID_; p.ldb = HID_; p.ldc = DIM_;
    gemm_fp16<false,true,false,true><<<dim3(8,32), 256, G_SMEM>>>(p);
    // 9. LN3 over (tmp + x2) -> out
    ln_kernel<<<NTOK,256>>>(tmp, x2, ln3_g, ln3_b, out, nullptr);
}